// round 12
// baseline (speedup 1.0000x reference)
#include <cuda_runtime.h>
#include <cuda_bf16.h>
#include <cstdint>

#define NN 50000
#define NE 800000
#define DIM 256
#define RB2 782   // ceil(NN/64)

typedef unsigned long long ull;

// ---------------- global scratch ----------------
__device__ __align__(16) float g_z[NN * DIM];          // z = x + aggr (k_init + edge atomics)
__device__ __align__(128) char g_weH[32768];           // We image  [64k][256n] bf16 hi
__device__ __align__(128) char g_weL[32768];
__device__ __align__(128) char g_w1H[131072];          // W1 images, 4 chunks x 32KB
__device__ __align__(128) char g_w1L[131072];
__device__ __align__(128) char g_w2H[131072];
__device__ __align__(128) char g_w2L[131072];

// ---------------- helpers ----------------
template <int S>
__device__ __forceinline__ uint32_t swz(uint32_t off) {
    return off ^ (((off >> S) & 7u) << 4);
}
__device__ __forceinline__ int permp(int np) {
    return (np & ~7) | ((np & 7) >> 1) | ((np & 1) << 2);
}
__device__ __forceinline__ uint32_t smem_u32(const void* p) {
    uint32_t a;
    asm("{ .reg .u64 t; cvta.to.shared.u64 t, %1; cvt.u32.u64 %0, t; }" : "=r"(a) : "l"(p));
    return a;
}
__device__ __forceinline__ void ldsm4(uint32_t r[4], uint32_t a) {
    asm volatile("ldmatrix.sync.aligned.m8n8.x4.shared.b16 {%0,%1,%2,%3}, [%4];"
                 : "=r"(r[0]), "=r"(r[1]), "=r"(r[2]), "=r"(r[3]) : "r"(a));
}
__device__ __forceinline__ void ldsm4t(uint32_t r[4], uint32_t a) {
    asm volatile("ldmatrix.sync.aligned.m8n8.x4.trans.shared.b16 {%0,%1,%2,%3}, [%4];"
                 : "=r"(r[0]), "=r"(r[1]), "=r"(r[2]), "=r"(r[3]) : "r"(a));
}
__device__ __forceinline__ void mma16816(float d[4], const uint32_t a[4], const uint32_t b[2]) {
    asm volatile("mma.sync.aligned.m16n8k16.row.col.f32.bf16.bf16.f32 "
                 "{%0,%1,%2,%3}, {%4,%5,%6,%7}, {%8,%9}, {%0,%1,%2,%3};"
                 : "+f"(d[0]), "+f"(d[1]), "+f"(d[2]), "+f"(d[3])
                 : "r"(a[0]), "r"(a[1]), "r"(a[2]), "r"(a[3]), "r"(b[0]), "r"(b[1]));
}
__device__ __forceinline__ void red4(float* a, float4 v) {
    asm volatile("red.global.add.v4.f32 [%0], {%1,%2,%3,%4};"
                 :: "l"(a), "f"(v.x), "f"(v.y), "f"(v.z), "f"(v.w));
}
__device__ __forceinline__ void cpa16(uint32_t dst, const void* src) {
    asm volatile("cp.async.cg.shared.global [%0], [%1], 16;" :: "r"(dst), "l"(src));
}
__device__ __forceinline__ void cpa_commit() { asm volatile("cp.async.commit_group;"); }
__device__ __forceinline__ void cpa_wait0()  { asm volatile("cp.async.wait_group 0;"); }
__device__ __forceinline__ void cpa_wait1()  { asm volatile("cp.async.wait_group 1;"); }

__device__ __forceinline__ void store_pair(char* bH, char* bL, uint32_t off, float2 v) {
    __nv_bfloat16 h0 = __float2bfloat16(v.x), h1 = __float2bfloat16(v.y);
    __nv_bfloat16 l0 = __float2bfloat16(v.x - __bfloat162float(h0));
    __nv_bfloat16 l1 = __float2bfloat16(v.y - __bfloat162float(h1));
    *(__nv_bfloat162*)(bH + off) = __halves2bfloat162(h0, h1);
    *(__nv_bfloat162*)(bL + off) = __halves2bfloat162(l0, l1);
}

// ---------------------------------------------------------------------------
// mma_sub: ONE split-pass: acc += A[32r x 64k] @ B[64k x 64c].
// A image: 128B rows swz<7>; B image: 512B rows swz<9>.
// ---------------------------------------------------------------------------
__device__ __forceinline__ void mma_sub(float acc[2][8][4],
    uint32_t aImg, uint32_t bImg, int mbase, int nbase, int l)
{
    const int lr = l & 7, lg8 = ((l >> 3) & 1) * 8, lh8 = (l >> 4) * 8;
    #pragma unroll
    for (int ks = 0; ks < 4; ks++) {
        uint32_t a[2][4], b[8][2];
        #pragma unroll
        for (int mf = 0; mf < 2; mf++)
            ldsm4(a[mf], aImg + swz<7>((uint32_t)((mbase + mf * 16 + lr + lg8) * 128
                                                  + (ks * 16 + lh8) * 2)));
        #pragma unroll
        for (int nq = 0; nq < 4; nq++) {
            uint32_t r4[4];
            ldsm4t(r4, bImg + swz<9>((uint32_t)((ks * 16 + lr + lg8) * 512
                                                + (nbase + nq * 16 + lh8) * 2)));
            b[2 * nq][0] = r4[0]; b[2 * nq][1] = r4[1];
            b[2 * nq + 1][0] = r4[2]; b[2 * nq + 1][1] = r4[3];
        }
        #pragma unroll
        for (int mf = 0; mf < 2; mf++)
            #pragma unroll
            for (int nf = 0; nf < 8; nf++)
                mma16816(acc[mf][nf], a[mf], b[nf]);
    }
}

// ---------------------------------------------------------------------------
// mma_chunk (k_edge): 3-pass with register-cached B fragments (R11 version)
// ---------------------------------------------------------------------------
__device__ __forceinline__ void mma_chunk(float acc[2][8][4],
    uint32_t aH, uint32_t aL, uint32_t bH, uint32_t bL,
    int mbase, int nbase, int l)
{
    const int lr = l & 7, lg8 = ((l >> 3) & 1) * 8, lh8 = (l >> 4) * 8;
    #pragma unroll
    for (int ks = 0; ks < 4; ks++) {
        uint32_t a[2][4], bh[8][2], bl[8][2];
        #pragma unroll
        for (int mf = 0; mf < 2; mf++)
            ldsm4(a[mf], aH + swz<7>((uint32_t)((mbase + mf * 16 + lr + lg8) * 128
                                                + (ks * 16 + lh8) * 2)));
        #pragma unroll
        for (int nq = 0; nq < 4; nq++) {
            uint32_t r4[4];
            uint32_t off = swz<9>((uint32_t)((ks * 16 + lr + lg8) * 512
                                             + (nbase + nq * 16 + lh8) * 2));
            ldsm4t(r4, bH + off);
            bh[2 * nq][0] = r4[0]; bh[2 * nq][1] = r4[1];
            bh[2 * nq + 1][0] = r4[2]; bh[2 * nq + 1][1] = r4[3];
            ldsm4t(r4, bL + off);
            bl[2 * nq][0] = r4[0]; bl[2 * nq][1] = r4[1];
            bl[2 * nq + 1][0] = r4[2]; bl[2 * nq + 1][1] = r4[3];
        }
        #pragma unroll
        for (int mf = 0; mf < 2; mf++)
            #pragma unroll
            for (int nf = 0; nf < 8; nf++)
                mma16816(acc[mf][nf], a[mf], bh[nf]);
        #pragma unroll
        for (int mf = 0; mf < 2; mf++)
            #pragma unroll
            for (int nf = 0; nf < 8; nf++)
                mma16816(acc[mf][nf], a[mf], bl[nf]);
        #pragma unroll
        for (int mf = 0; mf < 2; mf++)
            ldsm4(a[mf], aL + swz<7>((uint32_t)((mbase + mf * 16 + lr + lg8) * 128
                                                + (ks * 16 + lh8) * 2)));
        #pragma unroll
        for (int mf = 0; mf < 2; mf++)
            #pragma unroll
            for (int nf = 0; nf < 8; nf++)
                mma16816(acc[mf][nf], a[mf], bh[nf]);
    }
}

// ---------------------------------------------------------------------------
// k_prep: build bf16 hi/lo weight images
// ---------------------------------------------------------------------------
__global__ __launch_bounds__(256) void k_prep(const float* __restrict__ We,
                                              const float* __restrict__ W1,
                                              const float* __restrict__ W2)
{
    int i = blockIdx.x * 256 + threadIdx.x;
    if (i < 8192) {
        int k = i >> 7, np = i & 127;
        uint32_t off = swz<9>((uint32_t)(k * 512 + permp(np) * 4));
        store_pair(g_weH, g_weL, off, ((const float2*)We)[i]);
    } else if (i < 40960) {
        int j = i - 8192;
        int kc = j >> 13, k = (j >> 7) & 63, np = j & 127;
        uint32_t off = (uint32_t)(kc * 32768) + swz<9>((uint32_t)(k * 512 + permp(np) * 4));
        store_pair(g_w1H, g_w1L, off, ((const float2*)W1)[j]);
    } else if (i < 73728) {
        int j = i - 40960;
        int kc = j >> 13, k = (j >> 7) & 63, np = j & 127;
        uint32_t off = (uint32_t)(kc * 32768) + swz<9>((uint32_t)(k * 512 + permp(np) * 4));
        store_pair(g_w2H, g_w2L, off, ((const float2*)W2)[j]);
    }
}

// ---------------------------------------------------------------------------
// k_init: z = x
// ---------------------------------------------------------------------------
__global__ __launch_bounds__(256) void k_init(const float4* __restrict__ x) {
    int i = blockIdx.x * 256 + threadIdx.x;
    reinterpret_cast<float4*>(g_z)[i] = x[i];
}

// ---------------------------------------------------------------------------
// k_edge: unchanged from R11 (at its L2 wall ~270us)
// ---------------------------------------------------------------------------
#define E_AH 0
#define E_AL 16384
#define E_BH 32768
#define E_BL 65536
#define E_SMEM 98304

__global__ __launch_bounds__(256, 2) void k_edge(
    const float* __restrict__ x, const int* __restrict__ eidx,
    const float* __restrict__ ea, const float* __restrict__ be)
{
    extern __shared__ char sm[];
    const int t = threadIdx.x, w = t >> 5, l = t & 31;
    const int wm = w & 3, wn = w >> 2, j = l & 3;
    const uint32_t sb = smem_u32(sm);

    #pragma unroll
    for (int i0 = 0; i0 < 8; i0++) {
        int i = i0 * 256 + t;
        cpa16(sb + E_BH + i * 16, g_weH + i * 16);
        cpa16(sb + E_BL + i * 16, g_weL + i * 16);
    }
    cpa_commit();

    const float2* ea2 = (const float2*)(ea + (size_t)blockIdx.x * (128 * 64));
    #pragma unroll
    for (int i0 = 0; i0 < 16; i0++) {
        int i = i0 * 256 + t;
        int r = i >> 5, kp = i & 31;
        store_pair(sm + E_AH, sm + E_AL, swz<7>((uint32_t)(r * 128 + kp * 4)), ea2[i]);
    }
    cpa_wait0();
    __syncthreads();

    int si[4], di[4];
    #pragma unroll
    for (int q = 0; q < 4; q++) {
        int r = wm * 32 + (q >> 1) * 16 + (q & 1) * 8 + (l >> 2);
        long long e = (long long)blockIdx.x * 128 + r;
        si[q] = eidx[e]; di[q] = eidx[NE + e];
    }

    #pragma unroll 1
    for (int hf = 0; hf < 2; hf++) {
        const int colbase = hf * 128 + wn * 64;
        float4 xv[4], bv[4];
        #pragma unroll
        for (int nq = 0; nq < 4; nq++) {
            int c4 = (colbase + nq * 16 + 4 * j) >> 2;
            xv[nq] = __ldg((const float4*)(x + (size_t)si[0] * DIM) + c4);
            bv[nq] = __ldg((const float4*)be + c4);
        }

        float acc[2][8][4];
        #pragma unroll
        for (int mf = 0; mf < 2; mf++)
            #pragma unroll
            for (int nf = 0; nf < 8; nf++) {
                acc[mf][nf][0] = 0.f; acc[mf][nf][1] = 0.f;
                acc[mf][nf][2] = 0.f; acc[mf][nf][3] = 0.f;
            }
        mma_chunk(acc, sb + E_AH, sb + E_AL, sb + E_BH, sb + E_BL,
                  wm * 32, colbase, l);

        #pragma unroll
        for (int q = 0; q < 4; q++) {
            float4 cur[4];
            #pragma unroll
            for (int nq = 0; nq < 4; nq++) cur[nq] = xv[nq];
            if (q < 3) {
                #pragma unroll
                for (int nq = 0; nq < 4; nq++) {
                    int c4 = (colbase + nq * 16 + 4 * j) >> 2;
                    xv[nq] = __ldg((const float4*)(x + (size_t)si[q + 1] * DIM) + c4);
                }
            }
            const int mf = q >> 1, rh = q & 1;
            float* zd = g_z + (size_t)di[q] * DIM;
            #pragma unroll
            for (int nq = 0; nq < 4; nq++) {
                int col = colbase + nq * 16 + 4 * j;
                float4 o;
                o.x = fmaxf(acc[mf][2 * nq][2 * rh]     + cur[nq].x + bv[nq].x, 0.f);
                o.y = fmaxf(acc[mf][2 * nq][2 * rh + 1] + cur[nq].y + bv[nq].y, 0.f);
                o.z = fmaxf(acc[mf][2 * nq + 1][2 * rh]     + cur[nq].z + bv[nq].z, 0.f);
                o.w = fmaxf(acc[mf][2 * nq + 1][2 * rh + 1] + cur[nq].w + bv[nq].w, 0.f);
                red4(zd + col, o);
            }
        }
    }
}

// ---------------------------------------------------------------------------
// k_mlp v2 (FUSED, occ 2): 256 threads (wm2 x wn4), CTA = 64 rows x 256 cols.
// Sub-pass B staging: only one 32KB B-image live per slot.
// Smem (96KB): phase1: A dbuf 0..32K (16K each: hi+lo), BS0 32..64K, BS1 64..96K
//              phase2: H1 images 0..64K (4 x 16K: hi+lo), W2 slot 64..96K
//              epilogue: LN partials @ 0 (2KB)
// ---------------------------------------------------------------------------
#define M_A(buf)  ((buf) * 16384)
#define M_BS0     32768
#define M_BS1     65536
#define M_W2S     65536
#define M2_SMEM   98304

__global__ __launch_bounds__(256, 2) void k_mlp(
    const float* __restrict__ x, const float* __restrict__ b1,
    const float* __restrict__ b2, const float* __restrict__ gamma,
    const float* __restrict__ beta, float* __restrict__ out)
{
    extern __shared__ char sm[];
    const int t = threadIdx.x, w = t >> 5, l = t & 31;
    const int wm = w & 1, wn = w >> 1, j = l & 3;
    const uint32_t sb = smem_u32(sm);
    const int rowb = blockIdx.x * 64;
    const float2* Z2 = (const float2*)g_z;

    // prologue: Bh(0) -> BS0 [group], Bl(0) -> BS1 [group]
    #pragma unroll
    for (int i0 = 0; i0 < 8; i0++) {
        int i = i0 * 256 + t;
        cpa16(sb + M_BS0 + i * 16, g_w1H + i * 16);
    }
    cpa_commit();
    #pragma unroll
    for (int i0 = 0; i0 < 8; i0++) {
        int i = i0 * 256 + t;
        cpa16(sb + M_BS1 + i * 16, g_w1L + i * 16);
    }
    cpa_commit();

    // stage A chunk 0 (64 rows x 64 k -> bf16 hi/lo)
    #pragma unroll
    for (int i0 = 0; i0 < 8; i0++) {
        int i = i0 * 256 + t;
        int r = i >> 5, kp = i & 31;
        int row = min(rowb + r, NN - 1);
        float2 v = Z2[(size_t)row * 128 + kp];
        store_pair(sm + M_A(0), sm + M_A(0) + 8192,
                   swz<7>((uint32_t)(r * 128 + kp * 4)), v);
    }

    float acc[2][8][4];
    #pragma unroll
    for (int mf = 0; mf < 2; mf++)
        #pragma unroll
        for (int nf = 0; nf < 8; nf++) {
            acc[mf][nf][0] = 0.f; acc[mf][nf][1] = 0.f;
            acc[mf][nf][2] = 0.f; acc[mf][nf][3] = 0.f;
        }

    // -------- phase 1: acc = z @ W1 --------
    #pragma unroll 1
    for (int c = 0; c < 4; c++) {
        cpa_wait1();              // Bh(c) landed (Bl(c) may be pending)
        __syncthreads();
        if (c < 3) {              // stage A(c+1) into other buffer
            #pragma unroll
            for (int i0 = 0; i0 < 8; i0++) {
                int i = i0 * 256 + t;
                int r = i >> 5, kp = i & 31;
                int row = min(rowb + r, NN - 1);
                float2 v = Z2[(size_t)row * 128 + (c + 1) * 32 + kp];
                store_pair(sm + M_A((c + 1) & 1), sm + M_A((c + 1) & 1) + 8192,
                           swz<7>((uint32_t)(r * 128 + kp * 4)), v);
            }
        }
        const uint32_t aB = sb + M_A(c & 1);
        mma_sub(acc, aB,        sb + M_BS0, wm * 32, wn * 64, l);   // hh
        mma_sub(acc, aB + 8192, sb + M_BS0, wm * 32, wn * 64, l);   // lh
        __syncthreads();          // BS0 consumed by all warps
        if (c < 3) {
            #pragma unroll
            for (int i0 = 0; i0 < 8; i0++) {
                int i = i0 * 256 + t;
                cpa16(sb + M_BS0 + i * 16, g_w1H + (c + 1) * 32768 + i * 16);
            }
            cpa_commit();
            cpa_wait1();          // Bl(c) landed (Bh(c+1) pending)
        } else {
            cpa_wait0();          // Bl(3) landed
        }
        __syncthreads();
        mma_sub(acc, aB, sb + M_BS1, wm * 32, wn * 64, l);          // hl
        __syncthreads();          // BS1 consumed
        if (c < 3) {
            #pragma unroll
            for (int i0 = 0; i0 < 8; i0++) {
                int i = i0 * 256 + t;
                cpa16(sb + M_BS1 + i * 16, g_w1L + (c + 1) * 32768 + i * 16);
            }
            cpa_commit();
        }
    }

    // -------- transition: prefetch W2h(0); convert acc -> H1 smem images ------
    #pragma unroll
    for (int i0 = 0; i0 < 8; i0++) {
        int i = i0 * 256 + t;
        cpa16(sb + M_W2S + i * 16, g_w2H + i * 16);
    }
    cpa_commit();

    #pragma unroll
    for (int mf = 0; mf < 2; mf++)
        #pragma unroll
        for (int rh = 0; rh < 2; rh++) {
            int r = wm * 32 + mf * 16 + rh * 8 + (l >> 2);
            #pragma unroll
            for (int nq = 0; nq < 4; nq++) {
                int col = wn * 64 + nq * 16 + 4 * j;
                float4 bv = __ldg((const float4*)b1 + (col >> 2));
                float h0 = fmaxf(acc[mf][2 * nq][2 * rh]     + bv.x, 0.f);
                float h1 = fmaxf(acc[mf][2 * nq][2 * rh + 1] + bv.y, 0.f);
                float h2 = fmaxf(acc[mf][2 * nq + 1][2 * rh]     + bv.z, 0.f);
                float h3 = fmaxf(acc[mf][2 * nq + 1][2 * rh + 1] + bv.w, 0.f);
                __nv_bfloat16 b0 = __float2bfloat16(h0), b1v = __float2bfloat16(h1);
                __nv_bfloat16 b2v = __float2bfloat16(h2), b3 = __float2bfloat16(h3);
                __nv_bfloat16 c0 = __float2bfloat16(h0 - __bfloat162float(b0));
                __nv_bfloat16 c1 = __float2bfloat16(h1 - __bfloat162float(b1v));
                __nv_bfloat16 c2 = __float2bfloat16(h2 - __bfloat162float(b2v));
                __nv_bfloat16 c3 = __float2bfloat16(h3 - __bfloat162float(b3));
                int kc = col >> 6, kp = col & 63;
                uint32_t off = (uint32_t)(kc * 16384) + swz<7>((uint32_t)(r * 128 + kp * 2));
                __nv_bfloat162 hA = __halves2bfloat162(b0, b1v);
                __nv_bfloat162 hB = __halves2bfloat162(b2v, b3);
                *(ull*)(sm + off) = ((ull)*(uint32_t*)&hB << 32) | *(uint32_t*)&hA;
                __nv_bfloat162 lA = __halves2bfloat162(c0, c1);
                __nv_bfloat162 lB = __halves2bfloat162(c2, c3);
                *(ull*)(sm + off + 8192) = ((ull)*(uint32_t*)&lB << 32) | *(uint32_t*)&lA;
            }
        }

    #pragma unroll
    for (int mf = 0; mf < 2; mf++)
        #pragma unroll
        for (int nf = 0; nf < 8; nf++) {
            acc[mf][nf][0] = 0.f; acc[mf][nf][1] = 0.f;
            acc[mf][nf][2] = 0.f; acc[mf][nf][3] = 0.f;
        }

    // -------- phase 2: acc = h1 @ W2 (single W2 slot, sub-pass staged) -------
    #pragma unroll 1
    for (int c = 0; c < 4; c++) {
        cpa_wait0();
        __syncthreads();          // W2h(c) in slot (+ H1 visible at c=0)
        const uint32_t h1 = sb + (uint32_t)(c * 16384);
        mma_sub(acc, h1,        sb + M_W2S, wm * 32, wn * 64, l);   // hh
        mma_sub(acc, h1 + 8192, sb + M_W2S, wm * 32, wn * 64, l);   // lh
        __syncthreads();
        #pragma unroll
        for (int i0 = 0; i0 < 8; i0++) {
            int i = i0 * 256 + t;
            cpa16(sb + M_W2S + i * 16, g_w2L + c * 32768 + i * 16);
        }
        cpa_commit();
        cpa_wait0();
        __syncthreads();          // W2l(c) in slot
        mma_sub(acc, h1, sb + M_W2S, wm * 32, wn * 64, l);          // hl
        __syncthreads();
        if (c < 3) {
            #pragma unroll
            for (int i0 = 0; i0 < 8; i0++) {
                int i = i0 * 256 + t;
                cpa16(sb + M_W2S + i * 16, g_w2H + (c + 1) * 32768 + i * 16);
            }
            cpa_commit();
        }
    }

    // -------- epilogue: h = relu(acc+b2)+x ; LayerNorm ; out -----------------
    float2* sred = (float2*)sm;   // 2KB over dead H1(0)
    #pragma unroll
    for (int mf = 0; mf < 2; mf++)
        #pragma unroll
        for (int rh = 0; rh < 2; rh++) {
            int r = wm * 32 + mf * 16 + rh * 8 + (l >> 2);
            int gcl = min(rowb + r, NN - 1);
            const float4* xr = (const float4*)(x + (size_t)gcl * DIM);
            float s = 0.f, q = 0.f;
            #pragma unroll
            for (int nq = 0; nq < 4; nq++) {
                int col = wn * 64 + nq * 16 + 4 * j;
                float4 bv = __ldg((const float4*)b2 + (col >> 2));
                float4 xv = __ldg(xr + (col >> 2));
                float h0 = fmaxf(acc[mf][2 * nq][2 * rh]     + bv.x, 0.f) + xv.x;
                float h1 = fmaxf(acc[mf][2 * nq][2 * rh + 1] + bv.y, 0.f) + xv.y;
                float h2 = fmaxf(acc[mf][2 * nq + 1][2 * rh]     + bv.z, 0.f) + xv.z;
                float h3 = fmaxf(acc[mf][2 * nq + 1][2 * rh + 1] + bv.w, 0.f) + xv.w;
                acc[mf][2 * nq][2 * rh]         = h0;
                acc[mf][2 * nq][2 * rh + 1]     = h1;
                acc[mf][2 * nq + 1][2 * rh]     = h2;
                acc[mf][2 * nq + 1][2 * rh + 1] = h3;
                s += (h0 + h1) + (h2 + h3);
                q += h0 * h0 + h1 * h1 + h2 * h2 + h3 * h3;
            }
            s += __shfl_xor_sync(0xffffffffu, s, 1);
            q += __shfl_xor_sync(0xffffffffu, q, 1);
            s += __shfl_xor_sync(0xffffffffu, s, 2);
            q += __shfl_xor_sync(0xffffffffu, q, 2);
            if (j == 0) sred[r * 4 + wn] = make_float2(s, q);
        }
    __syncthreads();

    #pragma unroll
    for (int mf = 0; mf < 2; mf++)
        #pragma unroll
        for (int rh = 0; rh < 2; rh++) {
            int r = wm * 32 + mf * 16 + rh * 8 + (l >> 2);
            int grow = rowb + r;
            float2 p0 = sred[r * 4 + 0], p1 = sred[r * 4 + 1];
            float2 p2 = sred[r * 4 + 2], p3 = sred[r * 4 + 3];
            float s = (p0.x + p1.x) + (p2.x + p3.x);
            float q = (p0.y + p1.y) + (p2.y + p3.y);
            float mu = s * (1.0f / 256.0f);
            float var = q * (1.0f / 256.0f) - mu * mu;
            float inv = rsqrtf(var + 1e-5f);
            if (grow < NN) {
                #pragma unroll
                for (int nq = 0; nq < 4; nq++) {
                    int col = wn * 64 + nq * 16 + 4 * j;
                    float4 gv = __ldg((const float4*)gamma + (col >> 2));
                    float4 tv = __ldg((const float4*)beta + (col >> 2));
                    float4 o;
                    o.x = (acc[mf][2 * nq][2 * rh]         - mu) * inv * gv.x + tv.x;
                    o.y = (acc[mf][2 * nq][2 * rh + 1]     - mu) * inv * gv.y + tv.y;
                    o.z = (acc[mf][2 * nq + 1][2 * rh]     - mu) * inv * gv.z + tv.z;
                    o.w = (acc[mf][2 * nq + 1][2 * rh + 1] - mu) * inv * gv.w + tv.w;
                    ((float4*)(out + (size_t)grow * DIM))[col >> 2] = o;
                }
            }
        }
}

// ---------------------------------------------------------------------------
extern "C" void kernel_launch(void* const* d_in, const int* in_sizes, int n_in,
                              void* d_out, int out_size)
{
    const float* x     = (const float*)d_in[0];
    const int*   eidx  = (const int*)d_in[1];     // int32 (JAX x64 disabled)
    const float* ea    = (const float*)d_in[2];
    const float* We    = (const float*)d_in[3];
    const float* be    = (const float*)d_in[4];
    const float* W1    = (const float*)d_in[5];
    const float* b1    = (const float*)d_in[6];
    const float* W2    = (const float*)d_in[7];
    const float* b2    = (const float*)d_in[8];
    const float* gamma = (const float*)d_in[9];
    const float* beta  = (const float*)d_in[10];
    float* out         = (float*)d_out;

    cudaFuncSetAttribute(k_edge, cudaFuncAttributeMaxDynamicSharedMemorySize, E_SMEM);
    cudaFuncSetAttribute(k_mlp, cudaFuncAttributeMaxDynamicSharedMemorySize, M2_SMEM);

    k_prep<<<288, 256>>>(We, W1, W2);
    k_init<<<12500, 256>>>((const float4*)x);
    k_edge<<<6250, 256, E_SMEM>>>(x, eidx, ea, be);
    k_mlp<<<RB2, 256, M2_SMEM>>>(x, b1, b2, gamma, beta, out);
}